// round 6
// baseline (speedup 1.0000x reference)
#include <cuda_runtime.h>
#include <math.h>

#define BB 16
#define NN 64
#define TT 50
#define DD 4
#define NEMB 128
#define EPS 1e-20f

typedef unsigned long long ull;

__device__ __forceinline__ ull pk2(float a, float b) {
    ull r; asm("mov.b64 %0, {%1,%2};" : "=l"(r) : "f"(a), "f"(b)); return r;
}
__device__ __forceinline__ void upk2(ull p, float& a, float& b) {
    asm("mov.b64 {%0,%1}, %2;" : "=f"(a), "=f"(b) : "l"(p));
}
__device__ __forceinline__ ull fma2(ull a, ull b, ull c) {
    ull r; asm("fma.rn.f32x2 %0, %1, %2, %3;" : "=l"(r) : "l"(a), "l"(b), "l"(c));
    return r;
}

__device__ __forceinline__ float selu_f(float v) {
    const float scale  = 1.0507009873554805f;
    const float salpha = 1.7580993408473766f;   // scale * alpha
    float e   = __expf(v);
    float neg = salpha * e - salpha;
    float pos = scale * v;
    return v > 0.f ? pos : neg;
}

__global__ __launch_bounds__(512, 2)
void gcn_fused_kernel(const float* __restrict__ x,
                      const float* __restrict__ Wc,
                      const float* __restrict__ bc,
                      const float* __restrict__ Ws,
                      const float* __restrict__ bs,
                      float* __restrict__ out)
{
    const int bt  = blockIdx.x;          // 0..B*T-1
    const int b   = bt / TT;
    const int t   = bt % TT;
    const int tid = threadIdx.x;

    __shared__ float4 sx[NN];            // x[b, :, t, :]
    __shared__ float4 sxd[NN];           // dinv[m] * x[m]
    __shared__ float4 sy[NN];            // normalized conv input
    __shared__ float  w[NN][NN + 1];     // pairwise weights
    __shared__ float  pdeg[8 * NN];      // partial degree sums
    __shared__ float4 psum[8 * NN];      // partial y sums
    __shared__ float  dinv[NN];

    // ---- load x tile ----
    if (tid < NN) {
        const float4* p = reinterpret_cast<const float4*>(
            x + ((size_t)(b * NN + tid) * TT + t) * DD);
        sx[tid] = *p;
    }
    __syncthreads();

    // ---- phase 1: thread (r = tid&63, q = tid>>6 in 0..7) owns 8 m-values ----
    const int r = tid & 63;
    const int q = tid >> 6;
    {
        const float4 a = sx[r];
        float degp = 0.f;
        #pragma unroll
        for (int k = 0; k < 8; k++) {
            const int m = q * 8 + k;
            const float4 c = sx[m];
            const float d0 = a.x - c.x, d1 = a.y - c.y;
            const float d2 = a.z - c.z, d3 = a.w - c.w;
            const float dd = d0 * d0 + d1 * d1 + d2 * d2 + d3 * d3;
            const float wv = (m == r) ? 0.f : rsqrtf(dd);  // 1/(||.||+1e-20) ~ rsqrt
            w[r][m] = wv;
            degp += wv;
        }
        pdeg[q * NN + r] = degp;
    }
    __syncthreads();

    // ---- dinv + pre-scaled x ----
    if (tid < NN) {
        float deg = 0.f;
        #pragma unroll
        for (int j = 0; j < 8; j++) deg += pdeg[j * NN + tid];
        const float di = rsqrtf(deg + EPS);
        dinv[tid] = di;
        const float4 v = sx[tid];
        sxd[tid] = make_float4(v.x * di, v.y * di, v.z * di, v.w * di);
    }
    __syncthreads();

    // ---- phase 2: partial y over this thread's m-chunk ----
    {
        float4 acc = make_float4(0.f, 0.f, 0.f, 0.f);
        #pragma unroll
        for (int k = 0; k < 8; k++) {
            const int m = q * 8 + k;
            const float wv = w[r][m];
            const float4 v = sxd[m];
            acc.x += wv * v.x; acc.y += wv * v.y;
            acc.z += wv * v.z; acc.w += wv * v.w;
        }
        psum[q * NN + r] = acc;
    }
    __syncthreads();

    if (tid < NN) {
        float ax = 0.f, ay = 0.f, az = 0.f, aw = 0.f;
        #pragma unroll
        for (int j = 0; j < 8; j++) {
            const float4 a_ = psum[j * NN + tid];
            ax += a_.x; ay += a_.y; az += a_.z; aw += a_.w;
        }
        const float di = dinv[tid];
        sy[tid] = make_float4(ax * di, ay * di, az * di, aw * di);
    }
    __syncthreads();

    // ---- epilogue: 64 nodes x 256 channels, 8 node-rows in flight ----
    const int rowq = tid >> 6;           // 0..7 : node row slot
    const int cg   = tid & 63;           // float4 channel group
    const int cc   = cg * 4;
    const bool is_skip = (cc < NEMB);
    const int  ch      = is_skip ? cc : (cc - NEMB);
    const float* Wp = is_skip ? Ws : Wc;
    const float* bp = is_skip ? bs : bc;
    const float4* vbase = is_skip ? sx : sy;

    const float4 r0 = *reinterpret_cast<const float4*>(Wp + 0 * NEMB + ch);
    const float4 r1 = *reinterpret_cast<const float4*>(Wp + 1 * NEMB + ch);
    const float4 r2 = *reinterpret_cast<const float4*>(Wp + 2 * NEMB + ch);
    const float4 r3 = *reinterpret_cast<const float4*>(Wp + 3 * NEMB + ch);
    const float4 bb = *reinterpret_cast<const float4*>(bp + ch);

    const ull pa0 = pk2(r0.x, r0.y), pa1 = pk2(r1.x, r1.y);
    const ull pa2 = pk2(r2.x, r2.y), pa3 = pk2(r3.x, r3.y);
    const ull pb0 = pk2(r0.z, r0.w), pb1 = pk2(r1.z, r1.w);
    const ull pb2 = pk2(r2.z, r2.w), pb3 = pk2(r3.z, r3.w);
    const ull bias01 = pk2(bb.x, bb.y);
    const ull bias23 = pk2(bb.z, bb.w);

    float* obase = out + (((size_t)(b * NN) * TT + t) * 2 * NEMB + cc);
    const size_t orow = (size_t)TT * 2 * NEMB;

    #pragma unroll
    for (int it = 0; it < 8; it++) {
        const int n = it * 8 + rowq;
        const float4 v = vbase[n];
        const ull vx = pk2(v.x, v.x), vy = pk2(v.y, v.y);
        const ull vz = pk2(v.z, v.z), vw = pk2(v.w, v.w);

        ull a01 = fma2(vx, pa0, bias01);
        a01 = fma2(vy, pa1, a01);
        a01 = fma2(vz, pa2, a01);
        a01 = fma2(vw, pa3, a01);

        ull a23 = fma2(vx, pb0, bias23);
        a23 = fma2(vy, pb1, a23);
        a23 = fma2(vz, pb2, a23);
        a23 = fma2(vw, pb3, a23);

        float o0, o1, o2, o3;
        upk2(a01, o0, o1);
        upk2(a23, o2, o3);
        float4 o = make_float4(selu_f(o0), selu_f(o1), selu_f(o2), selu_f(o3));
        *reinterpret_cast<float4*>(obase + (size_t)n * orow) = o;
    }
}

extern "C" void kernel_launch(void* const* d_in, const int* in_sizes, int n_in,
                              void* d_out, int out_size)
{
    // metadata order: x, rel_rec, rel_send, W_conv, b_conv, W_skip, b_skip
    const float* x  = (const float*)d_in[0];
    const float* Wc = (const float*)d_in[3];
    const float* bc = (const float*)d_in[4];
    const float* Ws = (const float*)d_in[5];
    const float* bs = (const float*)d_in[6];
    float* out = (float*)d_out;

    gcn_fused_kernel<<<BB * TT, 512>>>(x, Wc, bc, Ws, bs, out);
}

// round 7
// speedup vs baseline: 1.2743x; 1.2743x over previous
#include <cuda_runtime.h>
#include <math.h>

#define BB 16
#define NN 64
#define TT 50
#define DD 4
#define NEMB 128
#define EPS 1e-20f

#define LOG2E     1.4426950408889634f
#define SELU_SCALE 1.0507009873554805f
#define SELU_SALPHA 1.7580993408473766f           // scale * alpha
#define POS_MUL   (SELU_SCALE / LOG2E)            // converts a=z*log2e -> scale*z

__device__ __forceinline__ float ex2f(float a) {
    float d; asm("ex2.approx.f32 %0, %1;" : "=f"(d) : "f"(a)); return d;
}
// d = (c >= 0) ? a : b
__device__ __forceinline__ float slctf(float a, float b, float c) {
    float d; asm("slct.f32.f32 %0, %1, %2, %3;" : "=f"(d) : "f"(a), "f"(b), "f"(c));
    return d;
}

// a = z * log2e  (z = pre-activation). selu(z) = z>0 ? scale*z : salpha*(e^z - 1)
__device__ __forceinline__ float selu_from_a(float a) {
    const float e   = ex2f(a);                    // e^z
    const float neg = SELU_SALPHA * e - SELU_SALPHA;
    const float pos = a * POS_MUL;
    return slctf(pos, neg, a);
}

__global__ __launch_bounds__(256)
void gcn_fused_kernel(const float* __restrict__ x,
                      const float* __restrict__ Wc,
                      const float* __restrict__ bc,
                      const float* __restrict__ Ws,
                      const float* __restrict__ bs,
                      float* __restrict__ out)
{
    const int bt  = blockIdx.x;          // 0..B*T-1
    const int b   = bt / TT;
    const int t   = bt % TT;
    const int tid = threadIdx.x;

    __shared__ float4 sx[NN];            // x[b, :, t, :]
    __shared__ float4 sxd[NN];           // dinv[m] * x[m]
    __shared__ float4 sy[NN];            // normalized conv input
    __shared__ float  pdeg[4 * NN];      // partial degree sums
    __shared__ float4 psum[4 * NN];      // partial y sums
    __shared__ float  dinv[NN];

    // ---- load x tile ----
    if (tid < NN) {
        const float4* p = reinterpret_cast<const float4*>(
            x + ((size_t)(b * NN + tid) * TT + t) * DD);
        sx[tid] = *p;
    }
    __syncthreads();

    // ---- phase 1: thread (r = tid&63, q = tid>>6) owns m in [16q, 16q+16) ----
    // inverse distances stay in registers (no smem matrix needed: phase 2 is
    // executed by the same thread).
    const int r = tid & 63;
    const int q = tid >> 6;
    float wv[16];
    {
        const float4 a = sx[r];
        float degp = 0.f;
        #pragma unroll
        for (int k = 0; k < 16; k++) {
            const int m = q * 16 + k;
            const float4 c = sx[m];
            const float d0 = a.x - c.x, d1 = a.y - c.y;
            const float d2 = a.z - c.z, d3 = a.w - c.w;
            const float dd = d0 * d0 + d1 * d1 + d2 * d2 + d3 * d3;
            const float w_ = (m == r) ? 0.f : rsqrtf(dd);  // 1/(||.||+1e-20) ~ rsqrt
            wv[k] = w_;
            degp += w_;
        }
        pdeg[q * NN + r] = degp;
    }
    __syncthreads();

    // ---- dinv + pre-scaled x ----
    if (tid < NN) {
        const float deg = pdeg[tid] + pdeg[NN + tid] + pdeg[2 * NN + tid] + pdeg[3 * NN + tid];
        const float di  = rsqrtf(deg + EPS);
        dinv[tid] = di;
        const float4 v = sx[tid];
        sxd[tid] = make_float4(v.x * di, v.y * di, v.z * di, v.w * di);
    }
    __syncthreads();

    // ---- phase 2: partial y from register-held weights ----
    {
        float4 acc = make_float4(0.f, 0.f, 0.f, 0.f);
        #pragma unroll
        for (int k = 0; k < 16; k++) {
            const int m = q * 16 + k;
            const float w_ = wv[k];
            const float4 v = sxd[m];
            acc.x += w_ * v.x; acc.y += w_ * v.y;
            acc.z += w_ * v.z; acc.w += w_ * v.w;
        }
        psum[q * NN + r] = acc;
    }
    __syncthreads();

    if (tid < NN) {
        const float4 a0 = psum[tid];
        const float4 a1 = psum[NN + tid];
        const float4 a2 = psum[2 * NN + tid];
        const float4 a3 = psum[3 * NN + tid];
        const float di = dinv[tid];
        sy[tid] = make_float4((a0.x + a1.x + a2.x + a3.x) * di,
                              (a0.y + a1.y + a2.y + a3.y) * di,
                              (a0.z + a1.z + a2.z + a3.z) * di,
                              (a0.w + a1.w + a2.w + a3.w) * di);
    }
    __syncthreads();

    // ---- epilogue: 64 nodes x 256 channels, weights pre-scaled by log2e ----
    const int rowq = tid >> 6;           // which of 4 node rows per iter
    const int cg   = tid & 63;           // float4 channel group
    const int cc   = cg * 4;
    const bool is_skip = (cc < NEMB);
    const int  ch      = is_skip ? cc : (cc - NEMB);
    const float* Wp = is_skip ? Ws : Wc;
    const float* bp = is_skip ? bs : bc;
    const float4* vbase = is_skip ? sx : sy;

    float4 r0 = *reinterpret_cast<const float4*>(Wp + 0 * NEMB + ch);
    float4 r1 = *reinterpret_cast<const float4*>(Wp + 1 * NEMB + ch);
    float4 r2 = *reinterpret_cast<const float4*>(Wp + 2 * NEMB + ch);
    float4 r3 = *reinterpret_cast<const float4*>(Wp + 3 * NEMB + ch);
    float4 bb = *reinterpret_cast<const float4*>(bp + ch);
    r0.x *= LOG2E; r0.y *= LOG2E; r0.z *= LOG2E; r0.w *= LOG2E;
    r1.x *= LOG2E; r1.y *= LOG2E; r1.z *= LOG2E; r1.w *= LOG2E;
    r2.x *= LOG2E; r2.y *= LOG2E; r2.z *= LOG2E; r2.w *= LOG2E;
    r3.x *= LOG2E; r3.y *= LOG2E; r3.z *= LOG2E; r3.w *= LOG2E;
    bb.x *= LOG2E; bb.y *= LOG2E; bb.z *= LOG2E; bb.w *= LOG2E;

    float* obase = out + (((size_t)(b * NN) * TT + t) * 2 * NEMB + cc);
    const size_t orow = (size_t)TT * 2 * NEMB;

    #pragma unroll
    for (int it = 0; it < 16; it++) {
        const int n = it * 4 + rowq;
        const float4 v = vbase[n];
        // a = (v . W + b) * log2e
        float a0 = v.x * r0.x + v.y * r1.x + v.z * r2.x + v.w * r3.x + bb.x;
        float a1 = v.x * r0.y + v.y * r1.y + v.z * r2.y + v.w * r3.y + bb.y;
        float a2 = v.x * r0.z + v.y * r1.z + v.z * r2.z + v.w * r3.z + bb.z;
        float a3 = v.x * r0.w + v.y * r1.w + v.z * r2.w + v.w * r3.w + bb.w;
        float4 o = make_float4(selu_from_a(a0), selu_from_a(a1),
                               selu_from_a(a2), selu_from_a(a3));
        *reinterpret_cast<float4*>(obase + (size_t)n * orow) = o;
    }
}

extern "C" void kernel_launch(void* const* d_in, const int* in_sizes, int n_in,
                              void* d_out, int out_size)
{
    // metadata order: x, rel_rec, rel_send, W_conv, b_conv, W_skip, b_skip
    const float* x  = (const float*)d_in[0];
    const float* Wc = (const float*)d_in[3];
    const float* bc = (const float*)d_in[4];
    const float* Ws = (const float*)d_in[5];
    const float* bs = (const float*)d_in[6];
    float* out = (float*)d_out;

    gcn_fused_kernel<<<BB * TT, 256>>>(x, Wc, bc, Ws, bs, out);
}